// round 16
// baseline (speedup 1.0000x reference)
#include <cuda_runtime.h>
#include <cuda_bf16.h>
#include <cstdint>

#define S_LEN 2048
#define D_MODEL 1024
#define N_HEADS 16
#define HEAD_DIM 64
#define TBL 4095        // 2*S - 1
#define KPACK 2048      // packed rel length per row
#define TPAD 4096       // padded rel_table rows (rows >= TBL zeroed)
#define LOG2E 1.4426950408889634f

// ---------------- scratch (__device__ arrays, no allocs) ---------------------
__device__ float g_QR[(size_t)N_HEADS * S_LEN * KPACK];  // 256 MiB packed rel (pre-scaled by log2e)

__device__ __nv_bfloat16 g_xh [S_LEN * D_MODEL], g_xl [S_LEN * D_MODEL];
__device__ __nv_bfloat16 g_Qh [S_LEN * D_MODEL], g_Ql [S_LEN * D_MODEL];
__device__ __nv_bfloat16 g_Kh [S_LEN * D_MODEL], g_Kl [S_LEN * D_MODEL];
__device__ __nv_bfloat16 g_Vh [S_LEN * D_MODEL], g_Vl [S_LEN * D_MODEL];
__device__ __nv_bfloat16 g_AOh[S_LEN * D_MODEL], g_AOl[S_LEN * D_MODEL];
__device__ __nv_bfloat16 g_Wth[4u * D_MODEL * D_MODEL], g_Wtl[4u * D_MODEL * D_MODEL];
__device__ __nv_bfloat16 g_Th [TPAD * HEAD_DIM], g_Tl [TPAD * HEAD_DIM];

// ============================ helpers ========================================
__device__ __forceinline__ uint32_t smem_u32(const void* p) {
    uint32_t a;
    asm("{ .reg .u64 t; cvta.to.shared.u64 t, %1; cvt.u32.u64 %0, t; }" : "=r"(a) : "l"(p));
    return a;
}
__device__ __forceinline__ void ldm_x4(uint32_t* r, uint32_t addr) {
    asm volatile("ldmatrix.sync.aligned.m8n8.x4.shared.b16 {%0,%1,%2,%3}, [%4];"
        : "=r"(r[0]), "=r"(r[1]), "=r"(r[2]), "=r"(r[3]) : "r"(addr));
}
__device__ __forceinline__ void ldm_x4_t(uint32_t* r, uint32_t addr) {
    asm volatile("ldmatrix.sync.aligned.m8n8.x4.trans.shared.b16 {%0,%1,%2,%3}, [%4];"
        : "=r"(r[0]), "=r"(r[1]), "=r"(r[2]), "=r"(r[3]) : "r"(addr));
}
__device__ __forceinline__ void mma_bf16(float* c, const uint32_t* a, const uint32_t* b) {
    asm volatile("mma.sync.aligned.m16n8k16.row.col.f32.bf16.bf16.f32 "
        "{%0,%1,%2,%3}, {%4,%5,%6,%7}, {%8,%9}, {%0,%1,%2,%3};"
        : "+f"(c[0]), "+f"(c[1]), "+f"(c[2]), "+f"(c[3])
        : "r"(a[0]), "r"(a[1]), "r"(a[2]), "r"(a[3]), "r"(b[0]), "r"(b[1]));
}
__device__ __forceinline__ float ex2(float x) {
    float r;
    asm("ex2.approx.ftz.f32 %0, %1;" : "=f"(r) : "f"(x));
    return r;
}
#define CP_ASYNC16(dst, src) \
    asm volatile("cp.async.cg.shared.global [%0], [%1], 16;" :: "r"(dst), "l"(src))
#define CP_COMMIT() asm volatile("cp.async.commit_group;")
#define CP_WAIT(N)  asm volatile("cp.async.wait_group %0;" :: "n"(N) : "memory")

__device__ __forceinline__ void split2(float v, __nv_bfloat16& h, __nv_bfloat16& l) {
    h = __float2bfloat16(v);
    l = __float2bfloat16(v - __bfloat162float(h));
}
__device__ __forceinline__ uint32_t pack2(__nv_bfloat16 lo, __nv_bfloat16 hi) {
    __nv_bfloat162 t{lo, hi};
    return *(uint32_t*)&t;
}

// ============================ split kernels ==================================
__global__ void split_plane_kernel(const float* __restrict__ src,
                                   __nv_bfloat16* __restrict__ ph,
                                   __nv_bfloat16* __restrict__ pl, int n4)
{
    int i = blockIdx.x * blockDim.x + threadIdx.x;
    if (i >= n4) return;
    float4 v = *(const float4*)(src + (size_t)i * 4);
    __nv_bfloat16 h, l;
    split2(v.x, h, l); ph[i*4+0] = h; pl[i*4+0] = l;
    split2(v.y, h, l); ph[i*4+1] = h; pl[i*4+1] = l;
    split2(v.z, h, l); ph[i*4+2] = h; pl[i*4+2] = l;
    split2(v.w, h, l); ph[i*4+3] = h; pl[i*4+3] = l;
}

__global__ void split_T_kernel(const float* __restrict__ rel,
                               __nv_bfloat16* __restrict__ th,
                               __nv_bfloat16* __restrict__ tl)
{
    int i = blockIdx.x * blockDim.x + threadIdx.x;
    if (i >= TPAD * HEAD_DIM) return;
    int t = i >> 6;
    float v = (t < TBL) ? rel[i] : 0.f;
    __nv_bfloat16 h, l; split2(v, h, l);
    th[i] = h; tl[i] = l;
}

struct WSrc { const float* w[4]; };
__global__ __launch_bounds__(256) void wsplit_kernel(WSrc ws,
                                                     __nv_bfloat16* __restrict__ dh,
                                                     __nv_bfloat16* __restrict__ dl)
{
    __shared__ float t[32][33];
    const float* W = ws.w[blockIdx.z];
    __nv_bfloat16* oh = dh + (size_t)blockIdx.z * D_MODEL * D_MODEL;
    __nv_bfloat16* ol = dl + (size_t)blockIdx.z * D_MODEL * D_MODEL;
    const int n0 = blockIdx.x * 32, k0 = blockIdx.y * 32;
    const int tx = threadIdx.x & 31, ty = threadIdx.x >> 5;
    #pragma unroll
    for (int rr = 0; rr < 32; rr += 8)
        t[ty + rr][tx] = W[(size_t)(k0 + ty + rr) * D_MODEL + n0 + tx];
    __syncthreads();
    #pragma unroll
    for (int rr = 0; rr < 32; rr += 8) {
        float v = t[tx][ty + rr];
        __nv_bfloat16 h, l; split2(v, h, l);
        oh[(size_t)(n0 + ty + rr) * D_MODEL + k0 + tx] = h;
        ol[(size_t)(n0 + ty + rr) * D_MODEL + k0 + tx] = l;
    }
}

// ============================ mma.sync projection GEMM =======================
#define GPITCH 40
#define PLANE_B (128 * GPITCH * 2)     // 10240 bytes per plane
#define STAGE_B (4 * PLANE_B)          // 40960 bytes per stage

struct TCArgs {
    const __nv_bfloat16 *Ah, *Al, *Bh, *Bl;
    const float* bias; float* C;       // C may be null (bf16-only output)
    __nv_bfloat16 *Ch, *Cl;            // may be null (fp32-only output)
    float scale;
};

__global__ __launch_bounds__(256) void tc_gemm_kernel(TCArgs a0, TCArgs a1, TCArgs a2)
{
    TCArgs a = (blockIdx.z == 0) ? a0 : ((blockIdx.z == 1) ? a1 : a2);
    extern __shared__ char dsm[];
    __shared__ float biasS[128];

    const int tid = threadIdx.x, lane = tid & 31, w = tid >> 5;
    const int wm = w >> 2, wn = w & 3;
    const int m0 = blockIdx.y * 128, n0 = blockIdx.x * 128;
    const uint32_t sbase = smem_u32(dsm);

    if (tid < 128) biasS[tid] = a.bias[n0 + tid];

    const __nv_bfloat16* gsrc[4] = { a.Ah, a.Al, a.Bh, a.Bl };
    const int rb[4] = { m0, m0, n0, n0 };

    #pragma unroll
    for (int p = 0; p < 4; p++) {
        const __nv_bfloat16* g = gsrc[p];
        #pragma unroll
        for (int v = 0; v < 2; v++) {
            const int idx = tid + v * 256;
            const int row = idx >> 2, c16 = idx & 3;
            CP_ASYNC16(sbase + p * PLANE_B + row * 80 + c16 * 16,
                       g + (size_t)(rb[p] + row) * D_MODEL + c16 * 8);
        }
    }
    CP_COMMIT();

    float acc[4][4][4];
    #pragma unroll
    for (int i = 0; i < 4; i++)
        #pragma unroll
        for (int j = 0; j < 4; j++)
            #pragma unroll
            for (int q = 0; q < 4; q++) acc[i][j][q] = 0.f;

    for (int c = 0; c < 32; c++) {
        CP_WAIT(0);
        __syncthreads();
        if (c + 1 < 32) {
            const int k0 = (c + 1) * 32;
            const uint32_t st = sbase + ((c + 1) & 1) * STAGE_B;
            #pragma unroll
            for (int p = 0; p < 4; p++) {
                const __nv_bfloat16* g = gsrc[p];
                #pragma unroll
                for (int v = 0; v < 2; v++) {
                    const int idx = tid + v * 256;
                    const int row = idx >> 2, c16 = idx & 3;
                    CP_ASYNC16(st + p * PLANE_B + row * 80 + c16 * 16,
                               g + (size_t)(rb[p] + row) * D_MODEL + k0 + c16 * 8);
                }
            }
            CP_COMMIT();
        }

        const uint32_t sb = sbase + (c & 1) * STAGE_B;
        #pragma unroll
        for (int ks = 0; ks < 2; ks++) {
            const uint32_t colb = (uint32_t)(ks * 16 + ((lane >> 4) * 8)) * 2;
            uint32_t ah[4][4], al[4][4], bh[2][4], bl[2][4];
            #pragma unroll
            for (int mt = 0; mt < 4; mt++) {
                const uint32_t r = wm * 64 + mt * 16 + (lane & 15);
                ldm_x4(ah[mt], sb + 0 * PLANE_B + r * 80 + colb);
                ldm_x4(al[mt], sb + 1 * PLANE_B + r * 80 + colb);
            }
            #pragma unroll
            for (int nt2 = 0; nt2 < 2; nt2++) {
                const uint32_t r = wn * 32 + nt2 * 16 + (lane & 15);
                ldm_x4(bh[nt2], sb + 2 * PLANE_B + r * 80 + colb);
                ldm_x4(bl[nt2], sb + 3 * PLANE_B + r * 80 + colb);
            }
            #pragma unroll
            for (int mt = 0; mt < 4; mt++)
                #pragma unroll
                for (int nt = 0; nt < 4; nt++) {
                    uint32_t bhf[2] = { bh[nt >> 1][nt & 1], bh[nt >> 1][(nt & 1) + 2] };
                    uint32_t blf[2] = { bl[nt >> 1][nt & 1], bl[nt >> 1][(nt & 1) + 2] };
                    mma_bf16(acc[mt][nt], ah[mt], bhf);
                    mma_bf16(acc[mt][nt], ah[mt], blf);
                    mma_bf16(acc[mt][nt], al[mt], bhf);
                }
        }
    }

    #pragma unroll
    for (int mt = 0; mt < 4; mt++) {
        const int r0 = m0 + wm * 64 + mt * 16 + (lane >> 2);
        #pragma unroll
        for (int nt = 0; nt < 4; nt++) {
            const int cl = wn * 32 + nt * 8 + 2 * (lane & 3);
            const int cg = n0 + cl;
            float2 v0, v1;
            v0.x = (acc[mt][nt][0] + biasS[cl + 0]) * a.scale;
            v0.y = (acc[mt][nt][1] + biasS[cl + 1]) * a.scale;
            v1.x = (acc[mt][nt][2] + biasS[cl + 0]) * a.scale;
            v1.y = (acc[mt][nt][3] + biasS[cl + 1]) * a.scale;
            if (a.C) {
                *(float2*)&a.C[(size_t)r0 * D_MODEL + cg]       = v0;
                *(float2*)&a.C[(size_t)(r0 + 8) * D_MODEL + cg] = v1;
            }
            if (a.Ch) {
                __nv_bfloat16 h0,l0,h1,l1;
                split2(v0.x,h0,l0); split2(v0.y,h1,l1);
                *(__nv_bfloat162*)&a.Ch[(size_t)r0 * D_MODEL + cg] = __nv_bfloat162{h0,h1};
                *(__nv_bfloat162*)&a.Cl[(size_t)r0 * D_MODEL + cg] = __nv_bfloat162{l0,l1};
                split2(v1.x,h0,l0); split2(v1.y,h1,l1);
                *(__nv_bfloat162*)&a.Ch[(size_t)(r0 + 8) * D_MODEL + cg] = __nv_bfloat162{h0,h1};
                *(__nv_bfloat162*)&a.Cl[(size_t)(r0 + 8) * D_MODEL + cg] = __nv_bfloat162{l0,l1};
            }
        }
    }
}

// ============================ mma.sync qrel ==================================
// Output pre-scaled by log2e (base-2 softmax downstream).
#define QPITCH 72
#define QPLANE_B (128 * QPITCH * 2)    // 18432 bytes

__global__ __launch_bounds__(256, 2) void tc_qrel_kernel(const __nv_bfloat16* __restrict__ Qh,
                                                         const __nv_bfloat16* __restrict__ Ql,
                                                         const __nv_bfloat16* __restrict__ Th,
                                                         const __nv_bfloat16* __restrict__ Tl,
                                                         float* __restrict__ R)
{
    extern __shared__ char dsm[];
    const int tid = threadIdx.x, lane = tid & 31, w = tid >> 5;
    const int wm = w >> 2, wn = w & 3;
    const int tt = blockIdx.x, i0 = blockIdx.y * 128, h = blockIdx.z;
    const int t0 = i0 + tt * 128;
    const uint32_t sbase = smem_u32(dsm);

    #pragma unroll
    for (int p = 0; p < 4; p++) {
        #pragma unroll
        for (int v = 0; v < 4; v++) {
            const int idx = tid + v * 256;
            const int row = idx >> 3, c16 = idx & 7;
            const __nv_bfloat16* src;
            if (p == 0)      src = Qh + (size_t)(i0 + row) * D_MODEL + h * HEAD_DIM + c16 * 8;
            else if (p == 1) src = Ql + (size_t)(i0 + row) * D_MODEL + h * HEAD_DIM + c16 * 8;
            else if (p == 2) src = Th + (size_t)(t0 + row) * HEAD_DIM + c16 * 8;
            else             src = Tl + (size_t)(t0 + row) * HEAD_DIM + c16 * 8;
            CP_ASYNC16(sbase + p * QPLANE_B + row * 144 + c16 * 16, src);
        }
    }
    CP_COMMIT(); CP_WAIT(0);
    __syncthreads();

    float acc[4][4][4];
    #pragma unroll
    for (int i = 0; i < 4; i++)
        #pragma unroll
        for (int j = 0; j < 4; j++)
            #pragma unroll
            for (int q = 0; q < 4; q++) acc[i][j][q] = 0.f;

    #pragma unroll
    for (int ks = 0; ks < 4; ks++) {
        const uint32_t colb = (uint32_t)(ks * 16 + ((lane >> 4) * 8)) * 2;
        uint32_t ah[4][4], al[4][4], bh[2][4], bl[2][4];
        #pragma unroll
        for (int mt = 0; mt < 4; mt++) {
            const uint32_t r = wm * 64 + mt * 16 + (lane & 15);
            ldm_x4(ah[mt], sbase + 0 * QPLANE_B + r * 144 + colb);
            ldm_x4(al[mt], sbase + 1 * QPLANE_B + r * 144 + colb);
        }
        #pragma unroll
        for (int nt2 = 0; nt2 < 2; nt2++) {
            const uint32_t r = wn * 32 + nt2 * 16 + (lane & 15);
            ldm_x4(bh[nt2], sbase + 2 * QPLANE_B + r * 144 + colb);
            ldm_x4(bl[nt2], sbase + 3 * QPLANE_B + r * 144 + colb);
        }
        #pragma unroll
        for (int mt = 0; mt < 4; mt++)
            #pragma unroll
            for (int nt = 0; nt < 4; nt++) {
                uint32_t bhf[2] = { bh[nt >> 1][nt & 1], bh[nt >> 1][(nt & 1) + 2] };
                uint32_t blf[2] = { bl[nt >> 1][nt & 1], bl[nt >> 1][(nt & 1) + 2] };
                mma_bf16(acc[mt][nt], ah[mt], bhf);
                mma_bf16(acc[mt][nt], ah[mt], blf);
                mma_bf16(acc[mt][nt], al[mt], bhf);
            }
    }

    #pragma unroll
    for (int mt = 0; mt < 4; mt++) {
        const int rloc = wm * 64 + mt * 16 + (lane >> 2);
        float* Rrow0 = R + (((size_t)(h * S_LEN + i0 + rloc))     << 11);
        float* Rrow1 = R + (((size_t)(h * S_LEN + i0 + rloc + 8)) << 11);
        #pragma unroll
        for (int nt = 0; nt < 4; nt++) {
            const int cloc = wn * 32 + nt * 8 + 2 * (lane & 3);
            const int k0 = tt * 128 + cloc - rloc;
            if ((unsigned)(k0)     < (unsigned)KPACK) Rrow0[k0]     = acc[mt][nt][0] * LOG2E;
            if ((unsigned)(k0 + 1) < (unsigned)KPACK) Rrow0[k0 + 1] = acc[mt][nt][1] * LOG2E;
            if ((unsigned)(k0 - 8) < (unsigned)KPACK) Rrow1[k0 - 8] = acc[mt][nt][2] * LOG2E;
            if ((unsigned)(k0 - 7) < (unsigned)KPACK) Rrow1[k0 - 7] = acc[mt][nt][3] * LOG2E;
        }
    }
}

// ============================ mma.sync flash attention =======================
// Base-2 online softmax (scores pre-scaled by log2e via K scale + QR scale).
// __launch_bounds__(256, 2): force <=128 regs so 256 CTAs fit in ONE wave.
#define APITCH_B 144
#define APLANE_B (64 * APITCH_B)       // 9216
#define ASTAGE_B (4 * APLANE_B)        // 36864

__global__ __launch_bounds__(256, 2) void attn_mma_kernel(
    const __nv_bfloat16* __restrict__ Qh, const __nv_bfloat16* __restrict__ Ql,
    const __nv_bfloat16* __restrict__ Kh, const __nv_bfloat16* __restrict__ Kl,
    const __nv_bfloat16* __restrict__ Vh, const __nv_bfloat16* __restrict__ Vl,
    const float* __restrict__ QR,
    __nv_bfloat16* __restrict__ AOh, __nv_bfloat16* __restrict__ AOl)
{
    extern __shared__ char dsm[];
    const int tid = threadIdx.x, lane = tid & 31, w = tid >> 5;
    const int i0 = blockIdx.x * 128, h = blockIdx.y;
    const uint32_t sb = smem_u32(dsm);

    // ---- stage Q (128 rows x 64 bf16 = 8x16B per row, 2 planes) ----
    #pragma unroll
    for (int p = 0; p < 2; p++) {
        const __nv_bfloat16* g = p ? Ql : Qh;
        #pragma unroll
        for (int v = 0; v < 4; v++) {
            const int idx = tid + v * 256;
            const int row = idx >> 3, c16 = idx & 7;
            CP_ASYNC16(sb + p * 18432 + row * APITCH_B + c16 * 16,
                       g + (size_t)(i0 + row) * D_MODEL + h * HEAD_DIM + c16 * 8);
        }
    }
    CP_COMMIT(); CP_WAIT(0);
    __syncthreads();

    uint32_t qfh[4][4], qfl[4][4];
    {
        const uint32_t rbyte = (uint32_t)(w * 16 + (lane & 15)) * APITCH_B;
        #pragma unroll
        for (int kf = 0; kf < 4; kf++) {
            const uint32_t colb = (uint32_t)(kf * 16 + ((lane >> 4) * 8)) * 2;
            ldm_x4(qfh[kf], sb + 0 * 18432 + rbyte + colb);
            ldm_x4(qfl[kf], sb + 1 * 18432 + rbyte + colb);
        }
    }
    __syncthreads();

    float o[8][4];
    #pragma unroll
    for (int i = 0; i < 8; i++)
        #pragma unroll
        for (int q = 0; q < 4; q++) o[i][q] = 0.f;
    float mrow0 = -1e30f, mrow1 = -1e30f, lrow0 = 0.f, lrow1 = 0.f;
    const int r0 = w * 16 + (lane >> 2);
    const float* qrow0 = QR + (((size_t)(h * S_LEN + i0 + r0)) << 11);
    const float* qrow1 = qrow0 + ((size_t)8 << 11);

    // prologue: tile 0 -> stage 0
    {
        const __nv_bfloat16* gs[4] = { Kh, Kl, Vh, Vl };
        #pragma unroll
        for (int p = 0; p < 4; p++)
            #pragma unroll
            for (int v = 0; v < 2; v++) {
                const int idx = tid + v * 256;
                const int row = idx >> 3, c16 = idx & 7;
                CP_ASYNC16(sb + p * APLANE_B + row * APITCH_B + c16 * 16,
                           gs[p] + (size_t)row * D_MODEL + h * HEAD_DIM + c16 * 8);
            }
        CP_COMMIT();
    }

    for (int jt = 0; jt < 32; jt++) {
        CP_WAIT(0);
        __syncthreads();
        if (jt + 1 < 32) {
            const int jn = (jt + 1) * 64;
            const uint32_t st2 = sb + ((jt + 1) & 1) * ASTAGE_B;
            const __nv_bfloat16* gs[4] = { Kh, Kl, Vh, Vl };
            #pragma unroll
            for (int p = 0; p < 4; p++)
                #pragma unroll
                for (int v = 0; v < 2; v++) {
                    const int idx = tid + v * 256;
                    const int row = idx >> 3, c16 = idx & 7;
                    CP_ASYNC16(st2 + p * APLANE_B + row * APITCH_B + c16 * 16,
                               gs[p] + (size_t)(jn + row) * D_MODEL + h * HEAD_DIM + c16 * 8);
                }
            CP_COMMIT();
        }

        const uint32_t st = sb + (jt & 1) * ASTAGE_B;
        const int j0 = jt * 64;

        // --- S init from packed rel (already log2e-scaled) ---
        float c[8][4];
        #pragma unroll
        for (int nf = 0; nf < 8; nf++) {
            const int jc = j0 + nf * 8 + (lane & 3) * 2;
            float2 g0 = *(const float2*)&qrow0[2046 - jc];
            float2 g1 = *(const float2*)&qrow1[2046 - jc];
            c[nf][0] = g0.y; c[nf][1] = g0.x;
            c[nf][2] = g1.y; c[nf][3] = g1.x;
        }

        // --- S += Q . K^T (split bf16; K carries 0.125*log2e) ---
        #pragma unroll
        for (int jf = 0; jf < 4; jf++) {
            const uint32_t rby = (uint32_t)(jf * 16 + (lane & 15)) * APITCH_B;
            #pragma unroll
            for (int kf = 0; kf < 4; kf++) {
                const uint32_t cb = (uint32_t)(kf * 16 + ((lane >> 4) * 8)) * 2;
                uint32_t kh4[4], kl4[4];
                ldm_x4(kh4, st + 0 * APLANE_B + rby + cb);
                ldm_x4(kl4, st + 1 * APLANE_B + rby + cb);
                uint32_t b0h[2] = { kh4[0], kh4[2] }, b1h[2] = { kh4[1], kh4[3] };
                uint32_t b0l[2] = { kl4[0], kl4[2] }, b1l[2] = { kl4[1], kl4[3] };
                mma_bf16(c[jf*2+0], qfh[kf], b0h);
                mma_bf16(c[jf*2+0], qfh[kf], b0l);
                mma_bf16(c[jf*2+0], qfl[kf], b0h);
                mma_bf16(c[jf*2+1], qfh[kf], b1h);
                mma_bf16(c[jf*2+1], qfh[kf], b1l);
                mma_bf16(c[jf*2+1], qfl[kf], b1h);
            }
        }

        // --- online softmax (base 2) ---
        float mx0 = -1e30f, mx1 = -1e30f;
        #pragma unroll
        for (int nf = 0; nf < 8; nf++) {
            mx0 = fmaxf(mx0, fmaxf(c[nf][0], c[nf][1]));
            mx1 = fmaxf(mx1, fmaxf(c[nf][2], c[nf][3]));
        }
        mx0 = fmaxf(mx0, __shfl_xor_sync(0xffffffffu, mx0, 1));
        mx0 = fmaxf(mx0, __shfl_xor_sync(0xffffffffu, mx0, 2));
        mx1 = fmaxf(mx1, __shfl_xor_sync(0xffffffffu, mx1, 1));
        mx1 = fmaxf(mx1, __shfl_xor_sync(0xffffffffu, mx1, 2));
        const float mn0 = fmaxf(mrow0, mx0), mn1 = fmaxf(mrow1, mx1);
        const float cor0 = ex2(mrow0 - mn0), cor1 = ex2(mrow1 - mn1);
        mrow0 = mn0; mrow1 = mn1;

        uint32_t P0h[8], P1h[8], P0l[8], P1l[8];
        float ls0 = 0.f, ls1 = 0.f;
        #pragma unroll
        for (int nf = 0; nf < 8; nf++) {
            float p0 = ex2(c[nf][0] - mn0), p1 = ex2(c[nf][1] - mn0);
            float p2 = ex2(c[nf][2] - mn1), p3 = ex2(c[nf][3] - mn1);
            ls0 += p0 + p1; ls1 += p2 + p3;
            __nv_bfloat16 h0,l0,h1,l1;
            split2(p0,h0,l0); split2(p1,h1,l1);
            P0h[nf] = pack2(h0,h1); P0l[nf] = pack2(l0,l1);
            split2(p2,h0,l0); split2(p3,h1,l1);
            P1h[nf] = pack2(h0,h1); P1l[nf] = pack2(l0,l1);
        }
        ls0 += __shfl_xor_sync(0xffffffffu, ls0, 1);
        ls0 += __shfl_xor_sync(0xffffffffu, ls0, 2);
        ls1 += __shfl_xor_sync(0xffffffffu, ls1, 1);
        ls1 += __shfl_xor_sync(0xffffffffu, ls1, 2);
        lrow0 = lrow0 * cor0 + ls0;
        lrow1 = lrow1 * cor1 + ls1;
        #pragma unroll
        for (int df = 0; df < 8; df++) {
            o[df][0] *= cor0; o[df][1] *= cor0;
            o[df][2] *= cor1; o[df][3] *= cor1;
        }

        // --- O += P . V (split bf16); V fragments via ldmatrix.trans ---
        #pragma unroll
        for (int kfj = 0; kfj < 4; kfj++) {
            uint32_t ah[4] = { P0h[2*kfj], P1h[2*kfj], P0h[2*kfj+1], P1h[2*kfj+1] };
            uint32_t al[4] = { P0l[2*kfj], P1l[2*kfj], P0l[2*kfj+1], P1l[2*kfj+1] };
            const uint32_t rby = (uint32_t)(kfj * 16 + (lane & 15)) * APITCH_B;
            #pragma unroll
            for (int dc = 0; dc < 4; dc++) {
                const uint32_t cb = (uint32_t)(dc * 16 + ((lane >> 4) * 8)) * 2;
                uint32_t vh4[4], vl4[4];
                ldm_x4_t(vh4, st + 2 * APLANE_B + rby + cb);
                ldm_x4_t(vl4, st + 3 * APLANE_B + rby + cb);
                uint32_t bh0[2] = { vh4[0], vh4[1] }, bh1[2] = { vh4[2], vh4[3] };
                uint32_t bl0[2] = { vl4[0], vl4[1] }, bl1[2] = { vl4[2], vl4[3] };
                mma_bf16(o[dc*2+0], ah, bh0);
                mma_bf16(o[dc*2+0], ah, bl0);
                mma_bf16(o[dc*2+0], al, bh0);
                mma_bf16(o[dc*2+1], ah, bh1);
                mma_bf16(o[dc*2+1], ah, bl1);
                mma_bf16(o[dc*2+1], al, bh1);
            }
        }
    }

    // ---- finalize: O /= l, split-store AO bf16 planes ----
    const float inv0 = 1.f / lrow0, inv1 = 1.f / lrow1;
    const int gr0 = i0 + r0, gr1 = gr0 + 8;
    #pragma unroll
    for (int df = 0; df < 8; df++) {
        const int d = h * HEAD_DIM + df * 8 + (lane & 3) * 2;
        __nv_bfloat16 h0,l0,h1,l1;
        split2(o[df][0] * inv0, h0, l0); split2(o[df][1] * inv0, h1, l1);
        *(__nv_bfloat162*)&AOh[(size_t)gr0 * D_MODEL + d] = __nv_bfloat162{h0,h1};
        *(__nv_bfloat162*)&AOl[(size_t)gr0 * D_MODEL + d] = __nv_bfloat162{l0,l1};
        split2(o[df][2] * inv1, h0, l0); split2(o[df][3] * inv1, h1, l1);
        *(__nv_bfloat162*)&AOh[(size_t)gr1 * D_MODEL + d] = __nv_bfloat162{h0,h1};
        *(__nv_bfloat162*)&AOl[(size_t)gr1 * D_MODEL + d] = __nv_bfloat162{l0,l1};
    }
}

// ============================ Launcher =======================================
extern "C" void kernel_launch(void* const* d_in, const int* in_sizes, int n_in,
                              void* d_out, int out_size)
{
    const float* x   = (const float*)d_in[0];
    const float* Wq  = (const float*)d_in[1];
    const float* bq  = (const float*)d_in[2];
    const float* Wk  = (const float*)d_in[3];
    const float* bk  = (const float*)d_in[4];
    const float* Wv  = (const float*)d_in[5];
    const float* bv  = (const float*)d_in[6];
    const float* Wo  = (const float*)d_in[7];
    const float* bo  = (const float*)d_in[8];
    const float* rel = (const float*)d_in[9];
    float* out = (float*)d_out;

    float* pQR;
    __nv_bfloat16 *pxh, *pxl, *pQh, *pQl, *pKh, *pKl, *pVh, *pVl;
    __nv_bfloat16 *pAOh, *pAOl, *pWth, *pWtl, *pTh, *pTl;
    cudaGetSymbolAddress((void**)&pQR,  g_QR);
    cudaGetSymbolAddress((void**)&pxh,  g_xh);
    cudaGetSymbolAddress((void**)&pxl,  g_xl);
    cudaGetSymbolAddress((void**)&pQh,  g_Qh);
    cudaGetSymbolAddress((void**)&pQl,  g_Ql);
    cudaGetSymbolAddress((void**)&pKh,  g_Kh);
    cudaGetSymbolAddress((void**)&pKl,  g_Kl);
    cudaGetSymbolAddress((void**)&pVh,  g_Vh);
    cudaGetSymbolAddress((void**)&pVl,  g_Vl);
    cudaGetSymbolAddress((void**)&pAOh, g_AOh);
    cudaGetSymbolAddress((void**)&pAOl, g_AOl);
    cudaGetSymbolAddress((void**)&pWth, g_Wth);
    cudaGetSymbolAddress((void**)&pWtl, g_Wtl);
    cudaGetSymbolAddress((void**)&pTh,  g_Th);
    cudaGetSymbolAddress((void**)&pTl,  g_Tl);

    const int gemm_smem = 2 * STAGE_B;       // 81,920
    const int qrel_smem = 4 * QPLANE_B;      // 73,728
    const int attn_smem = 2 * ASTAGE_B;      // 73,728
    cudaFuncSetAttribute(tc_gemm_kernel,  cudaFuncAttributeMaxDynamicSharedMemorySize, gemm_smem);
    cudaFuncSetAttribute(tc_qrel_kernel,  cudaFuncAttributeMaxDynamicSharedMemorySize, qrel_smem);
    cudaFuncSetAttribute(attn_mma_kernel, cudaFuncAttributeMaxDynamicSharedMemorySize, attn_smem);

    // 0) splits: x, W^T (x4), rel_table
    split_plane_kernel<<<(S_LEN * D_MODEL / 4 + 255) / 256, 256>>>(x, pxh, pxl, S_LEN * D_MODEL / 4);
    WSrc ws; ws.w[0] = Wq; ws.w[1] = Wk; ws.w[2] = Wv; ws.w[3] = Wo;
    wsplit_kernel<<<dim3(32, 32, 4), 256>>>(ws, pWth, pWtl);
    split_T_kernel<<<(TPAD * HEAD_DIM + 255) / 256, 256>>>(rel, pTh, pTl);

    const size_t MM = (size_t)D_MODEL * D_MODEL;

    // 1) QKV projections -> bf16 planes (K folded with 1/8 * log2e for base-2 softmax)
    TCArgs aq{ pxh, pxl, pWth + 0*MM, pWtl + 0*MM, bq, nullptr, pQh, pQl, 1.0f };
    TCArgs ak{ pxh, pxl, pWth + 1*MM, pWtl + 1*MM, bk, nullptr, pKh, pKl, 0.125f * LOG2E };
    TCArgs av{ pxh, pxl, pWth + 2*MM, pWtl + 2*MM, bv, nullptr, pVh, pVl, 1.0f };
    tc_gemm_kernel<<<dim3(8, 16, 3), 256, gemm_smem>>>(aq, ak, av);

    // 2) packed banded qrel (log2e-scaled output)
    tc_qrel_kernel<<<dim3(17, 16, 16), 256, qrel_smem>>>(pQh, pQl, pTh, pTl, pQR);

    // 3) mma flash attention (base-2 softmax) -> AO bf16 planes
    attn_mma_kernel<<<dim3(16, 16), 256, attn_smem>>>(pQh, pQl, pKh, pKl, pVh, pVl,
                                                      pQR, pAOh, pAOl);

    // 4) output projection -> fp32 out
    TCArgs ao{ pAOh, pAOl, pWth + 3*MM, pWtl + 3*MM, bo, out, nullptr, nullptr, 1.0f };
    tc_gemm_kernel<<<dim3(8, 16, 1), 256, gemm_smem>>>(ao, ao, ao);
}

// round 17
// speedup vs baseline: 1.0028x; 1.0028x over previous
#include <cuda_runtime.h>
#include <cuda_bf16.h>
#include <cstdint>

#define S_LEN 2048
#define D_MODEL 1024
#define N_HEADS 16
#define HEAD_DIM 64
#define TBL 4095        // 2*S - 1
#define KPACK 2048      // packed rel length per row
#define TPAD 4096       // padded rel_table rows (rows >= TBL zeroed)
#define LOG2E 1.4426950408889634f

// ---------------- scratch (__device__ arrays, no allocs) ---------------------
__device__ float g_QR[(size_t)N_HEADS * S_LEN * KPACK];  // 256 MiB packed rel (pre-scaled by log2e)

__device__ __nv_bfloat16 g_xh [S_LEN * D_MODEL], g_xl [S_LEN * D_MODEL];
__device__ __nv_bfloat16 g_Qh [S_LEN * D_MODEL], g_Ql [S_LEN * D_MODEL];
__device__ __nv_bfloat16 g_Kh [S_LEN * D_MODEL], g_Kl [S_LEN * D_MODEL];
__device__ __nv_bfloat16 g_Vh [S_LEN * D_MODEL], g_Vl [S_LEN * D_MODEL];
__device__ __nv_bfloat16 g_AOh[S_LEN * D_MODEL], g_AOl[S_LEN * D_MODEL];
__device__ __nv_bfloat16 g_Wth[4u * D_MODEL * D_MODEL], g_Wtl[4u * D_MODEL * D_MODEL];
__device__ __nv_bfloat16 g_Th [TPAD * HEAD_DIM], g_Tl [TPAD * HEAD_DIM];

// ============================ helpers ========================================
__device__ __forceinline__ uint32_t smem_u32(const void* p) {
    uint32_t a;
    asm("{ .reg .u64 t; cvta.to.shared.u64 t, %1; cvt.u32.u64 %0, t; }" : "=r"(a) : "l"(p));
    return a;
}
__device__ __forceinline__ void ldm_x4(uint32_t* r, uint32_t addr) {
    asm volatile("ldmatrix.sync.aligned.m8n8.x4.shared.b16 {%0,%1,%2,%3}, [%4];"
        : "=r"(r[0]), "=r"(r[1]), "=r"(r[2]), "=r"(r[3]) : "r"(addr));
}
__device__ __forceinline__ void ldm_x4_t(uint32_t* r, uint32_t addr) {
    asm volatile("ldmatrix.sync.aligned.m8n8.x4.trans.shared.b16 {%0,%1,%2,%3}, [%4];"
        : "=r"(r[0]), "=r"(r[1]), "=r"(r[2]), "=r"(r[3]) : "r"(addr));
}
__device__ __forceinline__ void mma_bf16(float* c, const uint32_t* a, const uint32_t* b) {
    asm volatile("mma.sync.aligned.m16n8k16.row.col.f32.bf16.bf16.f32 "
        "{%0,%1,%2,%3}, {%4,%5,%6,%7}, {%8,%9}, {%0,%1,%2,%3};"
        : "+f"(c[0]), "+f"(c[1]), "+f"(c[2]), "+f"(c[3])
        : "r"(a[0]), "r"(a[1]), "r"(a[2]), "r"(a[3]), "r"(b[0]), "r"(b[1]));
}
__device__ __forceinline__ float ex2(float x) {
    float r;
    asm("ex2.approx.ftz.f32 %0, %1;" : "=f"(r) : "f"(x));
    return r;
}
#define CP_ASYNC16(dst, src) \
    asm volatile("cp.async.cg.shared.global [%0], [%1], 16;" :: "r"(dst), "l"(src))
#define CP_COMMIT() asm volatile("cp.async.commit_group;")
#define CP_WAIT(N)  asm volatile("cp.async.wait_group %0;" :: "n"(N) : "memory")

__device__ __forceinline__ void split2(float v, __nv_bfloat16& h, __nv_bfloat16& l) {
    h = __float2bfloat16(v);
    l = __float2bfloat16(v - __bfloat162float(h));
}
__device__ __forceinline__ uint32_t pack2(__nv_bfloat16 lo, __nv_bfloat16 hi) {
    __nv_bfloat162 t{lo, hi};
    return *(uint32_t*)&t;
}

// ============================ split kernels ==================================
__global__ void split_plane_kernel(const float* __restrict__ src,
                                   __nv_bfloat16* __restrict__ ph,
                                   __nv_bfloat16* __restrict__ pl, int n4)
{
    int i = blockIdx.x * blockDim.x + threadIdx.x;
    if (i >= n4) return;
    float4 v = *(const float4*)(src + (size_t)i * 4);
    __nv_bfloat16 h, l;
    split2(v.x, h, l); ph[i*4+0] = h; pl[i*4+0] = l;
    split2(v.y, h, l); ph[i*4+1] = h; pl[i*4+1] = l;
    split2(v.z, h, l); ph[i*4+2] = h; pl[i*4+2] = l;
    split2(v.w, h, l); ph[i*4+3] = h; pl[i*4+3] = l;
}

__global__ void split_T_kernel(const float* __restrict__ rel,
                               __nv_bfloat16* __restrict__ th,
                               __nv_bfloat16* __restrict__ tl)
{
    int i = blockIdx.x * blockDim.x + threadIdx.x;
    if (i >= TPAD * HEAD_DIM) return;
    int t = i >> 6;
    float v = (t < TBL) ? rel[i] : 0.f;
    __nv_bfloat16 h, l; split2(v, h, l);
    th[i] = h; tl[i] = l;
}

struct WSrc { const float* w[4]; };
__global__ __launch_bounds__(256) void wsplit_kernel(WSrc ws,
                                                     __nv_bfloat16* __restrict__ dh,
                                                     __nv_bfloat16* __restrict__ dl)
{
    __shared__ float t[32][33];
    const float* W = ws.w[blockIdx.z];
    __nv_bfloat16* oh = dh + (size_t)blockIdx.z * D_MODEL * D_MODEL;
    __nv_bfloat16* ol = dl + (size_t)blockIdx.z * D_MODEL * D_MODEL;
    const int n0 = blockIdx.x * 32, k0 = blockIdx.y * 32;
    const int tx = threadIdx.x & 31, ty = threadIdx.x >> 5;
    #pragma unroll
    for (int rr = 0; rr < 32; rr += 8)
        t[ty + rr][tx] = W[(size_t)(k0 + ty + rr) * D_MODEL + n0 + tx];
    __syncthreads();
    #pragma unroll
    for (int rr = 0; rr < 32; rr += 8) {
        float v = t[tx][ty + rr];
        __nv_bfloat16 h, l; split2(v, h, l);
        oh[(size_t)(n0 + ty + rr) * D_MODEL + k0 + tx] = h;
        ol[(size_t)(n0 + ty + rr) * D_MODEL + k0 + tx] = l;
    }
}

// ============================ mma.sync projection GEMM =======================
#define GPITCH 40
#define PLANE_B (128 * GPITCH * 2)     // 10240 bytes per plane
#define STAGE_B (4 * PLANE_B)          // 40960 bytes per stage

struct TCArgs {
    const __nv_bfloat16 *Ah, *Al, *Bh, *Bl;
    const float* bias; float* C;       // C may be null (bf16-only output)
    __nv_bfloat16 *Ch, *Cl;            // may be null (fp32-only output)
    float scale;
};

__global__ __launch_bounds__(256) void tc_gemm_kernel(TCArgs a0, TCArgs a1, TCArgs a2)
{
    TCArgs a = (blockIdx.z == 0) ? a0 : ((blockIdx.z == 1) ? a1 : a2);
    extern __shared__ char dsm[];
    __shared__ float biasS[128];

    const int tid = threadIdx.x, lane = tid & 31, w = tid >> 5;
    const int wm = w >> 2, wn = w & 3;
    const int m0 = blockIdx.y * 128, n0 = blockIdx.x * 128;
    const uint32_t sbase = smem_u32(dsm);

    if (tid < 128) biasS[tid] = a.bias[n0 + tid];

    const __nv_bfloat16* gsrc[4] = { a.Ah, a.Al, a.Bh, a.Bl };
    const int rb[4] = { m0, m0, n0, n0 };

    #pragma unroll
    for (int p = 0; p < 4; p++) {
        const __nv_bfloat16* g = gsrc[p];
        #pragma unroll
        for (int v = 0; v < 2; v++) {
            const int idx = tid + v * 256;
            const int row = idx >> 2, c16 = idx & 3;
            CP_ASYNC16(sbase + p * PLANE_B + row * 80 + c16 * 16,
                       g + (size_t)(rb[p] + row) * D_MODEL + c16 * 8);
        }
    }
    CP_COMMIT();

    float acc[4][4][4];
    #pragma unroll
    for (int i = 0; i < 4; i++)
        #pragma unroll
        for (int j = 0; j < 4; j++)
            #pragma unroll
            for (int q = 0; q < 4; q++) acc[i][j][q] = 0.f;

    for (int c = 0; c < 32; c++) {
        CP_WAIT(0);
        __syncthreads();
        if (c + 1 < 32) {
            const int k0 = (c + 1) * 32;
            const uint32_t st = sbase + ((c + 1) & 1) * STAGE_B;
            #pragma unroll
            for (int p = 0; p < 4; p++) {
                const __nv_bfloat16* g = gsrc[p];
                #pragma unroll
                for (int v = 0; v < 2; v++) {
                    const int idx = tid + v * 256;
                    const int row = idx >> 2, c16 = idx & 3;
                    CP_ASYNC16(st + p * PLANE_B + row * 80 + c16 * 16,
                               g + (size_t)(rb[p] + row) * D_MODEL + k0 + c16 * 8);
                }
            }
            CP_COMMIT();
        }

        const uint32_t sb = sbase + (c & 1) * STAGE_B;
        #pragma unroll
        for (int ks = 0; ks < 2; ks++) {
            const uint32_t colb = (uint32_t)(ks * 16 + ((lane >> 4) * 8)) * 2;
            uint32_t ah[4][4], al[4][4], bh[2][4], bl[2][4];
            #pragma unroll
            for (int mt = 0; mt < 4; mt++) {
                const uint32_t r = wm * 64 + mt * 16 + (lane & 15);
                ldm_x4(ah[mt], sb + 0 * PLANE_B + r * 80 + colb);
                ldm_x4(al[mt], sb + 1 * PLANE_B + r * 80 + colb);
            }
            #pragma unroll
            for (int nt2 = 0; nt2 < 2; nt2++) {
                const uint32_t r = wn * 32 + nt2 * 16 + (lane & 15);
                ldm_x4(bh[nt2], sb + 2 * PLANE_B + r * 80 + colb);
                ldm_x4(bl[nt2], sb + 3 * PLANE_B + r * 80 + colb);
            }
            #pragma unroll
            for (int mt = 0; mt < 4; mt++)
                #pragma unroll
                for (int nt = 0; nt < 4; nt++) {
                    uint32_t bhf[2] = { bh[nt >> 1][nt & 1], bh[nt >> 1][(nt & 1) + 2] };
                    uint32_t blf[2] = { bl[nt >> 1][nt & 1], bl[nt >> 1][(nt & 1) + 2] };
                    mma_bf16(acc[mt][nt], ah[mt], bhf);
                    mma_bf16(acc[mt][nt], ah[mt], blf);
                    mma_bf16(acc[mt][nt], al[mt], bhf);
                }
        }
    }

    #pragma unroll
    for (int mt = 0; mt < 4; mt++) {
        const int r0 = m0 + wm * 64 + mt * 16 + (lane >> 2);
        #pragma unroll
        for (int nt = 0; nt < 4; nt++) {
            const int cl = wn * 32 + nt * 8 + 2 * (lane & 3);
            const int cg = n0 + cl;
            float2 v0, v1;
            v0.x = (acc[mt][nt][0] + biasS[cl + 0]) * a.scale;
            v0.y = (acc[mt][nt][1] + biasS[cl + 1]) * a.scale;
            v1.x = (acc[mt][nt][2] + biasS[cl + 0]) * a.scale;
            v1.y = (acc[mt][nt][3] + biasS[cl + 1]) * a.scale;
            if (a.C) {
                *(float2*)&a.C[(size_t)r0 * D_MODEL + cg]       = v0;
                *(float2*)&a.C[(size_t)(r0 + 8) * D_MODEL + cg] = v1;
            }
            if (a.Ch) {
                __nv_bfloat16 h0,l0,h1,l1;
                split2(v0.x,h0,l0); split2(v0.y,h1,l1);
                *(__nv_bfloat162*)&a.Ch[(size_t)r0 * D_MODEL + cg] = __nv_bfloat162{h0,h1};
                *(__nv_bfloat162*)&a.Cl[(size_t)r0 * D_MODEL + cg] = __nv_bfloat162{l0,l1};
                split2(v1.x,h0,l0); split2(v1.y,h1,l1);
                *(__nv_bfloat162*)&a.Ch[(size_t)(r0 + 8) * D_MODEL + cg] = __nv_bfloat162{h0,h1};
                *(__nv_bfloat162*)&a.Cl[(size_t)(r0 + 8) * D_MODEL + cg] = __nv_bfloat162{l0,l1};
            }
        }
    }
}

// ============================ mma.sync qrel ==================================
// Output pre-scaled by log2e (base-2 softmax downstream).
#define QPITCH 72
#define QPLANE_B (128 * QPITCH * 2)    // 18432 bytes

__global__ __launch_bounds__(256, 2) void tc_qrel_kernel(const __nv_bfloat16* __restrict__ Qh,
                                                         const __nv_bfloat16* __restrict__ Ql,
                                                         const __nv_bfloat16* __restrict__ Th,
                                                         const __nv_bfloat16* __restrict__ Tl,
                                                         float* __restrict__ R)
{
    extern __shared__ char dsm[];
    const int tid = threadIdx.x, lane = tid & 31, w = tid >> 5;
    const int wm = w >> 2, wn = w & 3;
    const int tt = blockIdx.x, i0 = blockIdx.y * 128, h = blockIdx.z;
    const int t0 = i0 + tt * 128;
    const uint32_t sbase = smem_u32(dsm);

    #pragma unroll
    for (int p = 0; p < 4; p++) {
        #pragma unroll
        for (int v = 0; v < 4; v++) {
            const int idx = tid + v * 256;
            const int row = idx >> 3, c16 = idx & 7;
            const __nv_bfloat16* src;
            if (p == 0)      src = Qh + (size_t)(i0 + row) * D_MODEL + h * HEAD_DIM + c16 * 8;
            else if (p == 1) src = Ql + (size_t)(i0 + row) * D_MODEL + h * HEAD_DIM + c16 * 8;
            else if (p == 2) src = Th + (size_t)(t0 + row) * HEAD_DIM + c16 * 8;
            else             src = Tl + (size_t)(t0 + row) * HEAD_DIM + c16 * 8;
            CP_ASYNC16(sbase + p * QPLANE_B + row * 144 + c16 * 16, src);
        }
    }
    CP_COMMIT(); CP_WAIT(0);
    __syncthreads();

    float acc[4][4][4];
    #pragma unroll
    for (int i = 0; i < 4; i++)
        #pragma unroll
        for (int j = 0; j < 4; j++)
            #pragma unroll
            for (int q = 0; q < 4; q++) acc[i][j][q] = 0.f;

    #pragma unroll
    for (int ks = 0; ks < 4; ks++) {
        const uint32_t colb = (uint32_t)(ks * 16 + ((lane >> 4) * 8)) * 2;
        uint32_t ah[4][4], al[4][4], bh[2][4], bl[2][4];
        #pragma unroll
        for (int mt = 0; mt < 4; mt++) {
            const uint32_t r = wm * 64 + mt * 16 + (lane & 15);
            ldm_x4(ah[mt], sbase + 0 * QPLANE_B + r * 144 + colb);
            ldm_x4(al[mt], sbase + 1 * QPLANE_B + r * 144 + colb);
        }
        #pragma unroll
        for (int nt2 = 0; nt2 < 2; nt2++) {
            const uint32_t r = wn * 32 + nt2 * 16 + (lane & 15);
            ldm_x4(bh[nt2], sbase + 2 * QPLANE_B + r * 144 + colb);
            ldm_x4(bl[nt2], sbase + 3 * QPLANE_B + r * 144 + colb);
        }
        #pragma unroll
        for (int mt = 0; mt < 4; mt++)
            #pragma unroll
            for (int nt = 0; nt < 4; nt++) {
                uint32_t bhf[2] = { bh[nt >> 1][nt & 1], bh[nt >> 1][(nt & 1) + 2] };
                uint32_t blf[2] = { bl[nt >> 1][nt & 1], bl[nt >> 1][(nt & 1) + 2] };
                mma_bf16(acc[mt][nt], ah[mt], bhf);
                mma_bf16(acc[mt][nt], ah[mt], blf);
                mma_bf16(acc[mt][nt], al[mt], bhf);
            }
    }

    #pragma unroll
    for (int mt = 0; mt < 4; mt++) {
        const int rloc = wm * 64 + mt * 16 + (lane >> 2);
        float* Rrow0 = R + (((size_t)(h * S_LEN + i0 + rloc))     << 11);
        float* Rrow1 = R + (((size_t)(h * S_LEN + i0 + rloc + 8)) << 11);
        #pragma unroll
        for (int nt = 0; nt < 4; nt++) {
            const int cloc = wn * 32 + nt * 8 + 2 * (lane & 3);
            const int k0 = tt * 128 + cloc - rloc;
            if ((unsigned)(k0)     < (unsigned)KPACK) Rrow0[k0]     = acc[mt][nt][0] * LOG2E;
            if ((unsigned)(k0 + 1) < (unsigned)KPACK) Rrow0[k0 + 1] = acc[mt][nt][1] * LOG2E;
            if ((unsigned)(k0 - 8) < (unsigned)KPACK) Rrow1[k0 - 8] = acc[mt][nt][2] * LOG2E;
            if ((unsigned)(k0 - 7) < (unsigned)KPACK) Rrow1[k0 - 7] = acc[mt][nt][3] * LOG2E;
        }
    }
}

// ============================ mma.sync flash attention =======================
// Base-2 online softmax (scores pre-scaled by log2e via K scale + QR scale).
// __launch_bounds__(256, 2): force <=128 regs so 256 CTAs fit in ONE wave.
#define APITCH_B 144
#define APLANE_B (64 * APITCH_B)       // 9216
#define ASTAGE_B (4 * APLANE_B)        // 36864

__global__ __launch_bounds__(256, 2) void attn_mma_kernel(
    const __nv_bfloat16* __restrict__ Qh, const __nv_bfloat16* __restrict__ Ql,
    const __nv_bfloat16* __restrict__ Kh, const __nv_bfloat16* __restrict__ Kl,
    const __nv_bfloat16* __restrict__ Vh, const __nv_bfloat16* __restrict__ Vl,
    const float* __restrict__ QR,
    __nv_bfloat16* __restrict__ AOh, __nv_bfloat16* __restrict__ AOl)
{
    extern __shared__ char dsm[];
    const int tid = threadIdx.x, lane = tid & 31, w = tid >> 5;
    const int i0 = blockIdx.x * 128, h = blockIdx.y;
    const uint32_t sb = smem_u32(dsm);

    // ---- stage Q (128 rows x 64 bf16 = 8x16B per row, 2 planes) ----
    #pragma unroll
    for (int p = 0; p < 2; p++) {
        const __nv_bfloat16* g = p ? Ql : Qh;
        #pragma unroll
        for (int v = 0; v < 4; v++) {
            const int idx = tid + v * 256;
            const int row = idx >> 3, c16 = idx & 7;
            CP_ASYNC16(sb + p * 18432 + row * APITCH_B + c16 * 16,
                       g + (size_t)(i0 + row) * D_MODEL + h * HEAD_DIM + c16 * 8);
        }
    }
    CP_COMMIT(); CP_WAIT(0);
    __syncthreads();

    uint32_t qfh[4][4], qfl[4][4];
    {
        const uint32_t rbyte = (uint32_t)(w * 16 + (lane & 15)) * APITCH_B;
        #pragma unroll
        for (int kf = 0; kf < 4; kf++) {
            const uint32_t colb = (uint32_t)(kf * 16 + ((lane >> 4) * 8)) * 2;
            ldm_x4(qfh[kf], sb + 0 * 18432 + rbyte + colb);
            ldm_x4(qfl[kf], sb + 1 * 18432 + rbyte + colb);
        }
    }
    __syncthreads();

    float o[8][4];
    #pragma unroll
    for (int i = 0; i < 8; i++)
        #pragma unroll
        for (int q = 0; q < 4; q++) o[i][q] = 0.f;
    float mrow0 = -1e30f, mrow1 = -1e30f, lrow0 = 0.f, lrow1 = 0.f;
    const int r0 = w * 16 + (lane >> 2);
    const float* qrow0 = QR + (((size_t)(h * S_LEN + i0 + r0)) << 11);
    const float* qrow1 = qrow0 + ((size_t)8 << 11);

    // prologue: tile 0 -> stage 0
    {
        const __nv_bfloat16* gs[4] = { Kh, Kl, Vh, Vl };
        #pragma unroll
        for (int p = 0; p < 4; p++)
            #pragma unroll
            for (int v = 0; v < 2; v++) {
                const int idx = tid + v * 256;
                const int row = idx >> 3, c16 = idx & 7;
                CP_ASYNC16(sb + p * APLANE_B + row * APITCH_B + c16 * 16,
                           gs[p] + (size_t)row * D_MODEL + h * HEAD_DIM + c16 * 8);
            }
        CP_COMMIT();
    }

    for (int jt = 0; jt < 32; jt++) {
        CP_WAIT(0);
        __syncthreads();
        if (jt + 1 < 32) {
            const int jn = (jt + 1) * 64;
            const uint32_t st2 = sb + ((jt + 1) & 1) * ASTAGE_B;
            const __nv_bfloat16* gs[4] = { Kh, Kl, Vh, Vl };
            #pragma unroll
            for (int p = 0; p < 4; p++)
                #pragma unroll
                for (int v = 0; v < 2; v++) {
                    const int idx = tid + v * 256;
                    const int row = idx >> 3, c16 = idx & 7;
                    CP_ASYNC16(st2 + p * APLANE_B + row * APITCH_B + c16 * 16,
                               gs[p] + (size_t)(jn + row) * D_MODEL + h * HEAD_DIM + c16 * 8);
                }
            CP_COMMIT();
        }

        const uint32_t st = sb + (jt & 1) * ASTAGE_B;
        const int j0 = jt * 64;

        // --- S init from packed rel (already log2e-scaled) ---
        float c[8][4];
        #pragma unroll
        for (int nf = 0; nf < 8; nf++) {
            const int jc = j0 + nf * 8 + (lane & 3) * 2;
            float2 g0 = *(const float2*)&qrow0[2046 - jc];
            float2 g1 = *(const float2*)&qrow1[2046 - jc];
            c[nf][0] = g0.y; c[nf][1] = g0.x;
            c[nf][2] = g1.y; c[nf][3] = g1.x;
        }

        // --- S += Q . K^T (split bf16; K carries 0.125*log2e) ---
        #pragma unroll
        for (int jf = 0; jf < 4; jf++) {
            const uint32_t rby = (uint32_t)(jf * 16 + (lane & 15)) * APITCH_B;
            #pragma unroll
            for (int kf = 0; kf < 4; kf++) {
                const uint32_t cb = (uint32_t)(kf * 16 + ((lane >> 4) * 8)) * 2;
                uint32_t kh4[4], kl4[4];
                ldm_x4(kh4, st + 0 * APLANE_B + rby + cb);
                ldm_x4(kl4, st + 1 * APLANE_B + rby + cb);
                uint32_t b0h[2] = { kh4[0], kh4[2] }, b1h[2] = { kh4[1], kh4[3] };
                uint32_t b0l[2] = { kl4[0], kl4[2] }, b1l[2] = { kl4[1], kl4[3] };
                mma_bf16(c[jf*2+0], qfh[kf], b0h);
                mma_bf16(c[jf*2+0], qfh[kf], b0l);
                mma_bf16(c[jf*2+0], qfl[kf], b0h);
                mma_bf16(c[jf*2+1], qfh[kf], b1h);
                mma_bf16(c[jf*2+1], qfh[kf], b1l);
                mma_bf16(c[jf*2+1], qfl[kf], b1h);
            }
        }

        // --- online softmax (base 2) ---
        float mx0 = -1e30f, mx1 = -1e30f;
        #pragma unroll
        for (int nf = 0; nf < 8; nf++) {
            mx0 = fmaxf(mx0, fmaxf(c[nf][0], c[nf][1]));
            mx1 = fmaxf(mx1, fmaxf(c[nf][2], c[nf][3]));
        }
        mx0 = fmaxf(mx0, __shfl_xor_sync(0xffffffffu, mx0, 1));
        mx0 = fmaxf(mx0, __shfl_xor_sync(0xffffffffu, mx0, 2));
        mx1 = fmaxf(mx1, __shfl_xor_sync(0xffffffffu, mx1, 1));
        mx1 = fmaxf(mx1, __shfl_xor_sync(0xffffffffu, mx1, 2));
        const float mn0 = fmaxf(mrow0, mx0), mn1 = fmaxf(mrow1, mx1);
        const float cor0 = ex2(mrow0 - mn0), cor1 = ex2(mrow1 - mn1);
        mrow0 = mn0; mrow1 = mn1;

        uint32_t P0h[8], P1h[8], P0l[8], P1l[8];
        float ls0 = 0.f, ls1 = 0.f;
        #pragma unroll
        for (int nf = 0; nf < 8; nf++) {
            float p0 = ex2(c[nf][0] - mn0), p1 = ex2(c[nf][1] - mn0);
            float p2 = ex2(c[nf][2] - mn1), p3 = ex2(c[nf][3] - mn1);
            ls0 += p0 + p1; ls1 += p2 + p3;
            __nv_bfloat16 h0,l0,h1,l1;
            split2(p0,h0,l0); split2(p1,h1,l1);
            P0h[nf] = pack2(h0,h1); P0l[nf] = pack2(l0,l1);
            split2(p2,h0,l0); split2(p3,h1,l1);
            P1h[nf] = pack2(h0,h1); P1l[nf] = pack2(l0,l1);
        }
        ls0 += __shfl_xor_sync(0xffffffffu, ls0, 1);
        ls0 += __shfl_xor_sync(0xffffffffu, ls0, 2);
        ls1 += __shfl_xor_sync(0xffffffffu, ls1, 1);
        ls1 += __shfl_xor_sync(0xffffffffu, ls1, 2);
        lrow0 = lrow0 * cor0 + ls0;
        lrow1 = lrow1 * cor1 + ls1;
        #pragma unroll
        for (int df = 0; df < 8; df++) {
            o[df][0] *= cor0; o[df][1] *= cor0;
            o[df][2] *= cor1; o[df][3] *= cor1;
        }

        // --- O += P . V (split bf16); V fragments via ldmatrix.trans ---
        #pragma unroll
        for (int kfj = 0; kfj < 4; kfj++) {
            uint32_t ah[4] = { P0h[2*kfj], P1h[2*kfj], P0h[2*kfj+1], P1h[2*kfj+1] };
            uint32_t al[4] = { P0l[2*kfj], P1l[2*kfj], P0l[2*kfj+1], P1l[2*kfj+1] };
            const uint32_t rby = (uint32_t)(kfj * 16 + (lane & 15)) * APITCH_B;
            #pragma unroll
            for (int dc = 0; dc < 4; dc++) {
                const uint32_t cb = (uint32_t)(dc * 16 + ((lane >> 4) * 8)) * 2;
                uint32_t vh4[4], vl4[4];
                ldm_x4_t(vh4, st + 2 * APLANE_B + rby + cb);
                ldm_x4_t(vl4, st + 3 * APLANE_B + rby + cb);
                uint32_t bh0[2] = { vh4[0], vh4[1] }, bh1[2] = { vh4[2], vh4[3] };
                uint32_t bl0[2] = { vl4[0], vl4[1] }, bl1[2] = { vl4[2], vl4[3] };
                mma_bf16(o[dc*2+0], ah, bh0);
                mma_bf16(o[dc*2+0], ah, bl0);
                mma_bf16(o[dc*2+0], al, bh0);
                mma_bf16(o[dc*2+1], ah, bh1);
                mma_bf16(o[dc*2+1], ah, bl1);
                mma_bf16(o[dc*2+1], al, bh1);
            }
        }
    }

    // ---- finalize: O /= l, split-store AO bf16 planes ----
    const float inv0 = 1.f / lrow0, inv1 = 1.f / lrow1;
    const int gr0 = i0 + r0, gr1 = gr0 + 8;
    #pragma unroll
    for (int df = 0; df < 8; df++) {
        const int d = h * HEAD_DIM + df * 8 + (lane & 3) * 2;
        __nv_bfloat16 h0,l0,h1,l1;
        split2(o[df][0] * inv0, h0, l0); split2(o[df][1] * inv0, h1, l1);
        *(__nv_bfloat162*)&AOh[(size_t)gr0 * D_MODEL + d] = __nv_bfloat162{h0,h1};
        *(__nv_bfloat162*)&AOl[(size_t)gr0 * D_MODEL + d] = __nv_bfloat162{l0,l1};
        split2(o[df][2] * inv1, h0, l0); split2(o[df][3] * inv1, h1, l1);
        *(__nv_bfloat162*)&AOh[(size_t)gr1 * D_MODEL + d] = __nv_bfloat162{h0,h1};
        *(__nv_bfloat162*)&AOl[(size_t)gr1 * D_MODEL + d] = __nv_bfloat162{l0,l1};
    }
}

// ============================ Launcher =======================================
extern "C" void kernel_launch(void* const* d_in, const int* in_sizes, int n_in,
                              void* d_out, int out_size)
{
    const float* x   = (const float*)d_in[0];
    const float* Wq  = (const float*)d_in[1];
    const float* bq  = (const float*)d_in[2];
    const float* Wk  = (const float*)d_in[3];
    const float* bk  = (const float*)d_in[4];
    const float* Wv  = (const float*)d_in[5];
    const float* bv  = (const float*)d_in[6];
    const float* Wo  = (const float*)d_in[7];
    const float* bo  = (const float*)d_in[8];
    const float* rel = (const float*)d_in[9];
    float* out = (float*)d_out;

    float* pQR;
    __nv_bfloat16 *pxh, *pxl, *pQh, *pQl, *pKh, *pKl, *pVh, *pVl;
    __nv_bfloat16 *pAOh, *pAOl, *pWth, *pWtl, *pTh, *pTl;
    cudaGetSymbolAddress((void**)&pQR,  g_QR);
    cudaGetSymbolAddress((void**)&pxh,  g_xh);
    cudaGetSymbolAddress((void**)&pxl,  g_xl);
    cudaGetSymbolAddress((void**)&pQh,  g_Qh);
    cudaGetSymbolAddress((void**)&pQl,  g_Ql);
    cudaGetSymbolAddress((void**)&pKh,  g_Kh);
    cudaGetSymbolAddress((void**)&pKl,  g_Kl);
    cudaGetSymbolAddress((void**)&pVh,  g_Vh);
    cudaGetSymbolAddress((void**)&pVl,  g_Vl);
    cudaGetSymbolAddress((void**)&pAOh, g_AOh);
    cudaGetSymbolAddress((void**)&pAOl, g_AOl);
    cudaGetSymbolAddress((void**)&pWth, g_Wth);
    cudaGetSymbolAddress((void**)&pWtl, g_Wtl);
    cudaGetSymbolAddress((void**)&pTh,  g_Th);
    cudaGetSymbolAddress((void**)&pTl,  g_Tl);

    const int gemm_smem = 2 * STAGE_B;       // 81,920
    const int qrel_smem = 4 * QPLANE_B;      // 73,728
    const int attn_smem = 2 * ASTAGE_B;      // 73,728
    cudaFuncSetAttribute(tc_gemm_kernel,  cudaFuncAttributeMaxDynamicSharedMemorySize, gemm_smem);
    cudaFuncSetAttribute(tc_qrel_kernel,  cudaFuncAttributeMaxDynamicSharedMemorySize, qrel_smem);
    cudaFuncSetAttribute(attn_mma_kernel, cudaFuncAttributeMaxDynamicSharedMemorySize, attn_smem);

    // 0) splits: x, W^T (x4), rel_table
    split_plane_kernel<<<(S_LEN * D_MODEL / 4 + 255) / 256, 256>>>(x, pxh, pxl, S_LEN * D_MODEL / 4);
    WSrc ws; ws.w[0] = Wq; ws.w[1] = Wk; ws.w[2] = Wv; ws.w[3] = Wo;
    wsplit_kernel<<<dim3(32, 32, 4), 256>>>(ws, pWth, pWtl);
    split_T_kernel<<<(TPAD * HEAD_DIM + 255) / 256, 256>>>(rel, pTh, pTl);

    const size_t MM = (size_t)D_MODEL * D_MODEL;

    // 1) QKV projections -> bf16 planes (K folded with 1/8 * log2e for base-2 softmax)
    TCArgs aq{ pxh, pxl, pWth + 0*MM, pWtl + 0*MM, bq, nullptr, pQh, pQl, 1.0f };
    TCArgs ak{ pxh, pxl, pWth + 1*MM, pWtl + 1*MM, bk, nullptr, pKh, pKl, 0.125f * LOG2E };
    TCArgs av{ pxh, pxl, pWth + 2*MM, pWtl + 2*MM, bv, nullptr, pVh, pVl, 1.0f };
    tc_gemm_kernel<<<dim3(8, 16, 3), 256, gemm_smem>>>(aq, ak, av);

    // 2) packed banded qrel (log2e-scaled output)
    tc_qrel_kernel<<<dim3(17, 16, 16), 256, qrel_smem>>>(pQh, pQl, pTh, pTl, pQR);

    // 3) mma flash attention (base-2 softmax) -> AO bf16 planes
    attn_mma_kernel<<<dim3(16, 16), 256, attn_smem>>>(pQh, pQl, pKh, pKl, pVh, pVl,
                                                      pQR, pAOh, pAOl);

    // 4) output projection -> fp32 out
    TCArgs ao{ pAOh, pAOl, pWth + 3*MM, pWtl + 3*MM, bo, out, nullptr, nullptr, 1.0f };
    tc_gemm_kernel<<<dim3(8, 16, 1), 256, gemm_smem>>>(ao, ao, ao);
}